// round 11
// baseline (speedup 1.0000x reference)
#include <cuda_runtime.h>

// NURBS surface eval: DEG=3, N_CP=32x32, N_EVAL=2,000,000.
// Clamped-uniform knots: knot(i) = clamp(i-3,0,29)/29, span = floor(u*29)+3.
// Output: d_out[0..4N) = points (x,y,z,1); d_out[4N..8N) = normals (nx,ny,nz,0).
//
// R11 = R10 (table-Horner basis, conflict-free 8x-replicated smem tables)
// + software pipelining to kill the coeff-LDS -> Horner -> contraction chain:
//  * iteration i+1's uv LDG and 6 coeff LDS issue BEFORE iteration i's
//    contraction; i+1's Horner runs AFTER it. Basis weights (16 regs), not
//    coeffs, are carried across the loop -> loop top starts the cell gather
//    immediately.
//  * 768 threads/block (not 1024): smem (128KB) caps occupancy at 1 block
//    either way, but 64K regfile / 768 = 85 regs/thread gives the prefetch
//    window room without spilling.
// Partition of unity: w == 1 (no divide), N3 = 1-(N0+N1+N2), D3 = -(D0+D1+D2).
// Uniform positive derivative scales cancel in the normalized cross product.

#define NCP 32
#define NTHREADS 768
#define NBLOCKS 148
#define CP_ENTRIES (NCP * NCP * 8)           // 8192 float4 = 128 KB
#define CT_STRIDE  (3 * 8)                   // 3 float4 x 8 bank-columns per span
#define CT_ENTRIES (32 * CT_STRIDE)          // 12 KB
#define TAB_BYTES ((CP_ENTRIES + CT_ENTRIES) * 16)

__device__ __forceinline__ float knotv(int i) {
    int t = i - 3;
    t = t < 0 ? 0 : (t > 29 ? 29 : t);
    return (float)t * (1.0f / 29.0f);
}

// Reference Cox-de Boor values (fill phase only; 4x29 evals per block).
__device__ void basisVal3(float u, int span, float* __restrict__ Nb) {
    float left[4], right[4];
    float ndu[4][4];
    ndu[0][0] = 1.0f;
#pragma unroll
    for (int j = 1; j <= 3; ++j) {
        left[j]  = u - knotv(span + 1 - j);
        right[j] = knotv(span + j) - u;
        float saved = 0.0f;
#pragma unroll
        for (int r = 0; r < j; ++r) {
            float den = right[r + 1] + left[j - r];
            float tmp = ndu[r][j - 1] / den;
            ndu[r][j] = saved + right[r + 1] * tmp;
            saved = left[j - r] * tmp;
        }
        ndu[j][j] = saved;
    }
    Nb[0] = ndu[0][3]; Nb[1] = ndu[1][3]; Nb[2] = ndu[2][3]; Nb[3] = ndu[3][3];
}

__device__ __forceinline__ void spans_from_uv(float2 uv, int& se, int& sn,
                                              float& tu, float& tv) {
    float ue = uv.x * 29.0f;
    float vn = uv.y * 29.0f;
    se = (int)floorf(ue);
    se = se < 0 ? 0 : (se > 28 ? 28 : se);
    sn = (int)floorf(vn);
    sn = sn < 0 ? 0 : (sn > 28 ? 28 : sn);
    tu = ue - (float)se;
    tv = vn - (float)sn;
}

// Horner on 6 coeff float4s -> 16 basis weights (N3/D3 via partition of unity).
__device__ __forceinline__ void horner_weights(
    const float4* __restrict__ cu, const float4* __restrict__ cv,
    float tu, float tv,
    float* __restrict__ Nu, float* __restrict__ Du,
    float* __restrict__ Nv, float* __restrict__ Dv)
{
    float snu = 0.f, sdu = 0.f, snv = 0.f, sdv = 0.f;
#pragma unroll
    for (int r = 0; r < 3; ++r) {
        float4 c = cu[r];
        float Nr = fmaf(fmaf(fmaf(c.w, tu, c.z), tu, c.y), tu, c.x);
        float Dr = fmaf(fmaf(3.0f * c.w, tu, c.z + c.z), tu, c.y);
        Nu[r] = Nr; Du[r] = Dr; snu += Nr; sdu += Dr;
    }
#pragma unroll
    for (int r = 0; r < 3; ++r) {
        float4 c = cv[r];
        float Nr = fmaf(fmaf(fmaf(c.w, tv, c.z), tv, c.y), tv, c.x);
        float Dr = fmaf(fmaf(3.0f * c.w, tv, c.z + c.z), tv, c.y);
        Nv[r] = Nr; Dv[r] = Dr; snv += Nr; sdv += Dr;
    }
    Nu[3] = 1.0f - snu; Du[3] = -sdu;
    Nv[3] = 1.0f - snv; Dv[3] = -sdv;
}

extern "C" __global__ void __launch_bounds__(NTHREADS, 1)
nurbs_surface_kernel(const float2* __restrict__ ep,
                     const float*  __restrict__ cp,
                     float4* __restrict__ out,
                     int n)
{
    extern __shared__ float4 smem_tab[];
    float4* __restrict__ tab  = smem_tab;                 // control points
    float4* __restrict__ ctab = smem_tab + CP_ENTRIES;    // basis cubic coeffs

    const int tid   = threadIdx.x;
    const int lane8 = tid & 7;

    // ---- control-point table (8x replicated, bank-column striped) ----
    for (int e = tid; e < CP_ENTRIES; e += NTHREADS) {
        int cell = e >> 3;
        tab[e] = make_float4(cp[3 * cell + 0], cp[3 * cell + 1], cp[3 * cell + 2], 1.0f);
    }

    // ---- coeff table: exact cubic fit per span (N0..N2 stored) ----
    if (tid < 29) {
        int se = tid;
        float y[4][4];
#pragma unroll
        for (int k = 0; k < 4; ++k) {
            float uk = ((float)se + (float)k * (1.0f / 3.0f)) * (1.0f / 29.0f);
            basisVal3(uk, se + 3, y[k]);
        }
#pragma unroll
        for (int r = 0; r < 3; ++r) {
            float y0 = y[0][r], y1 = y[1][r], y2 = y[2][r], y3 = y[3][r];
            float a0 = y0;
            float a1 = 0.5f * (-11.0f * y0 + 18.0f * y1 - 9.0f * y2 + 2.0f * y3);
            float a2 = 4.5f * (2.0f * y0 - 5.0f * y1 + 4.0f * y2 - y3);
            float a3 = 4.5f * (-y0 + 3.0f * y1 - 3.0f * y2 + y3);
            float4 c = make_float4(a0, a1, a2, a3);
            int base = se * CT_STRIDE + r * 8;
#pragma unroll
            for (int col = 0; col < 8; ++col) ctab[base + col] = c;
        }
    }
    __syncthreads();

    float4* __restrict__ outn = out + n;
    const int stride = NBLOCKS * NTHREADS;
    int idx = blockIdx.x * NTHREADS + tid;
    if (idx >= n) return;

    // ---- prologue: stage 0 fully resolved ----
    int   se, sn;
    float tu, tv;
    spans_from_uv(ep[idx], se, sn, tu, tv);
    float Nu[4], Du[4], Nv[4], Dv[4];
    {
        float4 cu[3], cv[3];
        const float4* cub = ctab + se * CT_STRIDE + lane8;
        const float4* cvb = ctab + sn * CT_STRIDE + lane8;
#pragma unroll
        for (int r = 0; r < 3; ++r) { cu[r] = cub[r * 8]; cv[r] = cvb[r * 8]; }
        horner_weights(cu, cv, tu, tv, Nu, Du, Nv, Dv);
    }

    while (true) {
        // cell gather starts immediately: weights are ready from last iter
        const float4* __restrict__ p = tab + ((se * NCP + sn) * 8 + lane8);

        // ---- prefetch next point: uv, spans, 6 coeff LDS (latency hidden
        //      under the contraction below) ----
        int nidx = idx + stride;
        bool has_next = nidx < n;
        int   se2, sn2;
        float tu2, tv2;
        float4 cu2[3], cv2[3];
        {
            float2 uvn = ep[has_next ? nidx : idx];
            spans_from_uv(uvn, se2, sn2, tu2, tv2);
            const float4* cub = ctab + se2 * CT_STRIDE + lane8;
            const float4* cvb = ctab + sn2 * CT_STRIDE + lane8;
#pragma unroll
            for (int r = 0; r < 3; ++r) { cu2[r] = cub[r * 8]; cv2[r] = cvb[r * 8]; }
        }

        // ---- separable tensor contraction, conflict-free gather ----
        float px=0.f,py=0.f,pz=0.f;   // surface point (homogeneous w == 1)
        float ex=0.f,ey=0.f,ez=0.f;   // ~ d/du
        float fx=0.f,fy=0.f,fz=0.f;   // ~ d/dv
#pragma unroll
        for (int r = 0; r < 4; ++r) {
            float ax=0.f, ay=0.f, az=0.f;
            float bx=0.f, by=0.f, bz=0.f;
#pragma unroll
            for (int s = 0; s < 4; ++s) {
                float4 g = p[(r * NCP + s) * 8];
                float nv = Nv[s], dv = Dv[s];
                ax = fmaf(nv, g.x, ax); ay = fmaf(nv, g.y, ay); az = fmaf(nv, g.z, az);
                bx = fmaf(dv, g.x, bx); by = fmaf(dv, g.y, by); bz = fmaf(dv, g.z, bz);
            }
            float nu = Nu[r], du = Du[r];
            px = fmaf(nu, ax, px); py = fmaf(nu, ay, py); pz = fmaf(nu, az, pz);
            ex = fmaf(du, ax, ex); ey = fmaf(du, ay, ey); ez = fmaf(du, az, ez);
            fx = fmaf(nu, bx, fx); fy = fmaf(nu, by, fy); fz = fmaf(nu, bz, fz);
        }

        // normal = normalize(cross(d_e, d_n)); uniform scales cancel
        float cx = ey * fz - ez * fy;
        float cy = ez * fx - ex * fz;
        float cz = ex * fy - ey * fx;
        float il = rsqrtf(cx * cx + cy * cy + cz * cz);

        out[idx]  = make_float4(px, py, pz, 1.0f);
        outn[idx] = make_float4(cx * il, cy * il, cz * il, 0.0f);

        if (!has_next) break;
        idx = nidx;

        // ---- Horner for the next iteration (coeff LDS long since arrived) ----
        horner_weights(cu2, cv2, tu2, tv2, Nu, Du, Nv, Dv);
        se = se2; sn = sn2; tu = tu2; tv = tv2;
    }
}

extern "C" void kernel_launch(void* const* d_in, const int* in_sizes, int n_in,
                              void* d_out, int out_size)
{
    const float2* ep = (const float2*)d_in[0];   // evaluation_points (N,2)
    const float*  cp = (const float*)d_in[1];    // control_points (32,32,3)
    int n = in_sizes[0] / 2;
    float4* out = (float4*)d_out;

    cudaFuncSetAttribute(nurbs_surface_kernel,
                         cudaFuncAttributeMaxDynamicSharedMemorySize, TAB_BYTES);

    nurbs_surface_kernel<<<NBLOCKS, NTHREADS, TAB_BYTES>>>(ep, cp, out, n);
}